// round 12
// baseline (speedup 1.0000x reference)
#include <cuda_runtime.h>
#include <cuda_fp16.h>
#include <cstdint>

// Inputs (metadata order):
//   d_in[0] weight : float32 [N_NODES * 128]
//   d_in[1] cj     : float32 [N_NODES]
//   d_in[2] ci     : float32 [N_NODES]
//   d_in[3] src    : int32   [N_EDGES]
//   d_in[4] dst    : int32   [N_EDGES]
// Output: float32 [N_NODES * 128]
//
// h[d] = ci[d] * sum_{e: dst_e = d} weight[src_e] * cj[src_e]
//
// 4-kernel pipeline:
//   k_pre     : FUSED (a) dst histogram with per-edge rank capture
//                     (b) W' = fp16(weight * cj) into 25.6MB scratch
//   k_scan    : exclusive scan; publish/poll cross-block prefix (replay-
//               proven in R5/R9/R10 benches)
//   k_scatter : pos = offsets[dst] + rank (no atomics)
//   k_gather  : one warp per dst node; fp16 rows (256B -> 2 wavefronts/edge),
//               fp32 register accumulation, single 512B store

static constexpr int MAX_NODES  = 100000;
static constexpr int MAX_EDGES  = 1600000;
static constexpr int FEAT4      = 32;           // 128 floats = 32 float4
static constexpr int FEATH2     = 32;           // 128 halves = 32 uint2 (4 halves each)
static constexpr int SCAN_BLOCK = 1024;
static constexpr int MAX_SCAN_BLOCKS = (MAX_NODES + SCAN_BLOCK - 1) / SCAN_BLOCK; // 98

__device__ int g_counts[MAX_NODES];             // zero-init; re-zeroed by gather
__device__ int g_offsets[MAX_NODES];            // segment start
__device__ int g_cursor[MAX_NODES];             // segment end
__device__ unsigned int g_pub[MAX_SCAN_BLOCKS]; // zero-init; re-zeroed by scatter
__device__ int g_rank[MAX_EDGES];               // per-edge rank within its dst
__device__ int g_edge_src[MAX_EDGES];           // dst-sorted src ids
__device__ uint2 g_wh[MAX_NODES * FEATH2];      // fp16 W' = weight*cj (25.6 MB)

// ---------------- fused histogram + fp16 pre-scale ----------------

__global__ void __launch_bounds__(256)
k_pre(const float4* __restrict__ weight4,
      const float*  __restrict__ cj,
      const int4*   __restrict__ dst4,
      const int*    __restrict__ dst,
      int n_quads, int n_edges, int n_nodes, int hist_blocks)
{
    if ((int)blockIdx.x < hist_blocks) {
        // ---- histogram of dst, capturing per-edge ranks ----
        int q = blockIdx.x * 256 + threadIdx.x;
        if (q < n_quads) {
            int4 d = __ldg(dst4 + q);
            int4 r;
            r.x = atomicAdd(&g_counts[d.x], 1);
            r.y = atomicAdd(&g_counts[d.y], 1);
            r.z = atomicAdd(&g_counts[d.z], 1);
            r.w = atomicAdd(&g_counts[d.w], 1);
            ((int4*)g_rank)[q] = r;              // coalesced rank store
        }
        int t = n_quads * 4 + q;
        if (q < (n_edges - n_quads * 4))
            g_rank[t] = atomicAdd(&g_counts[dst[t]], 1);
    } else {
        // ---- W' = fp16(weight * cj): thread i -> 4 floats -> uint2 ----
        int i = ((int)blockIdx.x - hist_blocks) * 256 + threadIdx.x;
        int total = n_nodes * FEAT4;
        if (i < total) {
            int row = i >> 5;                    // 32 float4 per row
            float s = __ldg(cj + row);           // warp-uniform broadcast
            float4 v = __ldg(weight4 + i);
            __half2 h0 = __floats2half2_rn(v.x * s, v.y * s);
            __half2 h1 = __floats2half2_rn(v.z * s, v.w * s);
            uint2 p;
            p.x = *reinterpret_cast<unsigned int*>(&h0);
            p.y = *reinterpret_cast<unsigned int*>(&h1);
            g_wh[i] = p;
        }
    }
}

// ---------------- exclusive scan (single launch, publish/poll) ----------------
// Replay-proven structure (R5/R9/R10 benches). 98 co-resident blocks of 1024.
// Block totals < 2^31; bit31 is the publish flag.

__global__ void __launch_bounds__(SCAN_BLOCK)
k_scan(int n) {
    __shared__ int warp_sums[32];
    __shared__ int s_prefix;
    int tid  = threadIdx.x;
    int i    = blockIdx.x * SCAN_BLOCK + tid;
    int lane = tid & 31, wid = tid >> 5;

    int v = (i < n) ? g_counts[i] : 0;

    int x = v;  // inclusive warp scan
    #pragma unroll
    for (int o = 1; o < 32; o <<= 1) {
        int y = __shfl_up_sync(0xFFFFFFFFu, x, o);
        if (lane >= o) x += y;
    }
    if (lane == 31) warp_sums[wid] = x;
    __syncthreads();

    if (wid == 0) {
        int w = warp_sums[lane];
        #pragma unroll
        for (int o = 1; o < 32; o <<= 1) {
            int y = __shfl_up_sync(0xFFFFFFFFu, w, o);
            if (lane >= o) w += y;
        }
        warp_sums[lane] = w;
        if (lane == 31)
            atomicExch(&g_pub[blockIdx.x], 0x80000000u | (unsigned)w);
    }
    __syncthreads();

    if (wid == 0) {
        int acc = 0;
        for (int b = lane; b < (int)blockIdx.x; b += 32) {
            unsigned int p;
            do { p = *(volatile unsigned int*)&g_pub[b]; }
            while (!(p & 0x80000000u));
            acc += (int)(p & 0x7FFFFFFFu);
        }
        #pragma unroll
        for (int o = 16; o > 0; o >>= 1)
            acc += __shfl_down_sync(0xFFFFFFFFu, acc, o);
        if (lane == 0) s_prefix = acc;
    }
    __syncthreads();

    int warp_off = (wid > 0) ? warp_sums[wid - 1] : 0;
    if (i < n) {
        int excl = s_prefix + warp_off + x - v;
        g_offsets[i] = excl;        // segment start
        g_cursor[i]  = excl + v;    // segment end
    }
}

// ---------------- scatter (atomic-free) ----------------

__global__ void __launch_bounds__(256)
k_scatter(const int4* __restrict__ src4,
          const int4* __restrict__ dst4, int n_quads,
          const int* __restrict__ src,
          const int* __restrict__ dst, int n_edges)
{
    int q = blockIdx.x * 256 + threadIdx.x;
    if (q < n_quads) {
        int4 s = __ldg(src4 + q);
        int4 d = __ldg(dst4 + q);
        int4 r = ((const int4*)g_rank)[q];
        g_edge_src[g_offsets[d.x] + r.x] = s.x;
        g_edge_src[g_offsets[d.y] + r.y] = s.y;
        g_edge_src[g_offsets[d.z] + r.z] = s.z;
        g_edge_src[g_offsets[d.w] + r.w] = s.w;
    }
    int t = n_quads * 4 + q;
    if (q < (n_edges - n_quads * 4))
        g_edge_src[g_offsets[dst[t]] + g_rank[t]] = src[t];

    // reset scan publish flags for the next graph replay
    if (blockIdx.x == 0 && threadIdx.x < MAX_SCAN_BLOCKS)
        g_pub[threadIdx.x] = 0u;
}

// ---------------- main gather-accumulate (fp16 rows) ----------------
// One warp per destination node; lane c owns halves [4c, 4c+4) of the row
// (one uint2 = 8 bytes). fp32 accumulation; single float4 store.

__global__ void __launch_bounds__(256)
k_gather(const float* __restrict__ ci,
         float4*      __restrict__ out4,
         int n_nodes)
{
    int gid  = blockIdx.x * blockDim.x + threadIdx.x;
    int node = gid >> 5;
    int c    = gid & 31;
    if (node >= n_nodes) return;

    int base = g_offsets[node];
    int end  = g_cursor[node];

    float4 acc = make_float4(0.f, 0.f, 0.f, 0.f);

    int j = base;
    for (; j + 3 < end; j += 4) {
        int s0 = g_edge_src[j];
        int s1 = g_edge_src[j + 1];
        int s2 = g_edge_src[j + 2];
        int s3 = g_edge_src[j + 3];
        uint2 p0 = __ldg(&g_wh[(int64_t)s0 * FEATH2 + c]);
        uint2 p1 = __ldg(&g_wh[(int64_t)s1 * FEATH2 + c]);
        uint2 p2 = __ldg(&g_wh[(int64_t)s2 * FEATH2 + c]);
        uint2 p3 = __ldg(&g_wh[(int64_t)s3 * FEATH2 + c]);
        #pragma unroll
        for (int k = 0; k < 4; k++) {
            uint2 p = (k == 0) ? p0 : (k == 1) ? p1 : (k == 2) ? p2 : p3;
            float2 f0 = __half22float2(*reinterpret_cast<__half2*>(&p.x));
            float2 f1 = __half22float2(*reinterpret_cast<__half2*>(&p.y));
            acc.x += f0.x; acc.y += f0.y; acc.z += f1.x; acc.w += f1.y;
        }
    }
    for (; j < end; j++) {
        int s0 = g_edge_src[j];
        uint2 p = __ldg(&g_wh[(int64_t)s0 * FEATH2 + c]);
        float2 f0 = __half22float2(*reinterpret_cast<__half2*>(&p.x));
        float2 f1 = __half22float2(*reinterpret_cast<__half2*>(&p.y));
        acc.x += f0.x; acc.y += f0.y; acc.z += f1.x; acc.w += f1.y;
    }

    float m = __ldg(ci + node);
    acc.x *= m; acc.y *= m; acc.z *= m; acc.w *= m;
    out4[(int64_t)node * FEAT4 + c] = acc;

    // restore zero-counts invariant for the next graph replay
    if (c == 0) g_counts[node] = 0;
}

// ---------------- launch ----------------

extern "C" void kernel_launch(void* const* d_in, const int* in_sizes, int n_in,
                              void* d_out, int out_size)
{
    const float4* weight4 = (const float4*)d_in[0];
    const float*  cj      = (const float*)d_in[1];
    const float*  ci      = (const float*)d_in[2];
    const int*    src     = (const int*)d_in[3];
    const int*    dst     = (const int*)d_in[4];
    float4*       out4    = (float4*)d_out;

    int n_nodes = in_sizes[1];   // cj is [N,1]
    int n_edges = in_sizes[3];
    int n_quads = n_edges / 4;

    const int B = 256;
    int hist_blocks = (n_quads + B - 1) / B;
    int conv_blocks = (n_nodes * FEAT4 + B - 1) / B;
    int scan_blocks = (n_nodes + SCAN_BLOCK - 1) / SCAN_BLOCK;

    k_pre<<<hist_blocks + conv_blocks, B>>>(weight4, cj, (const int4*)dst, dst,
                                            n_quads, n_edges, n_nodes, hist_blocks);
    k_scan<<<scan_blocks, SCAN_BLOCK>>>(n_nodes);
    k_scatter<<<hist_blocks, B>>>((const int4*)src, (const int4*)dst, n_quads,
                                  src, dst, n_edges);

    int64_t total_threads = (int64_t)n_nodes * 32;
    int gather_blocks = (int)((total_threads + B - 1) / B);
    k_gather<<<gather_blocks, B>>>(ci, out4, n_nodes);
}

// round 13
// speedup vs baseline: 1.0579x; 1.0579x over previous
#include <cuda_runtime.h>
#include <cuda_fp16.h>
#include <cstdint>

// Inputs (metadata order):
//   d_in[0] weight : float32 [N_NODES * 128]
//   d_in[1] cj     : float32 [N_NODES]
//   d_in[2] ci     : float32 [N_NODES]
//   d_in[3] src    : int32   [N_EDGES]
//   d_in[4] dst    : int32   [N_EDGES]
// Output: float32 [N_NODES * 128]
//
// h[d] = ci[d] * sum_{e: dst_e = d} weight[src_e] * cj[src_e]
//
// 4-kernel pipeline:
//   k_pre     : FUSED (a) dst histogram with per-edge rank capture
//                     (b) W' = fp16(weight * cj), vectorized 16B stores
//   k_scan    : exclusive scan; publish/poll cross-block prefix
//   k_scatter : pos = offsets[dst] + rank (no atomics)
//   k_gather  : one warp per dst node; int4 edge-id broadcasts, fp16 rows,
//               pairwise HADD2 pre-reduction, fp32 accumulation, 1 store

static constexpr int MAX_NODES  = 100000;
static constexpr int MAX_EDGES  = 1600000;
static constexpr int FEAT4      = 32;           // 128 floats = 32 float4
static constexpr int FEATH2     = 32;           // 128 halves = 32 uint2
static constexpr int SCAN_BLOCK = 1024;
static constexpr int MAX_SCAN_BLOCKS = (MAX_NODES + SCAN_BLOCK - 1) / SCAN_BLOCK; // 98

__device__ int g_counts[MAX_NODES];             // zero-init; re-zeroed by gather
__device__ int g_offsets[MAX_NODES];            // segment start
__device__ int g_cursor[MAX_NODES];             // segment end
__device__ unsigned int g_pub[MAX_SCAN_BLOCKS]; // zero-init; re-zeroed by scatter
__device__ int g_rank[MAX_EDGES];               // per-edge rank within its dst
__device__ __align__(16) int g_edge_src[MAX_EDGES];  // dst-sorted src ids
__device__ uint2 g_wh[MAX_NODES * FEATH2];      // fp16 W' = weight*cj (25.6 MB)

// ---------------- fused histogram + fp16 pre-scale ----------------

__global__ void __launch_bounds__(256)
k_pre(const float4* __restrict__ weight4,
      const float*  __restrict__ cj,
      const int4*   __restrict__ dst4,
      const int*    __restrict__ dst,
      int n_quads, int n_edges, int n_nodes, int hist_blocks)
{
    if ((int)blockIdx.x < hist_blocks) {
        // ---- histogram of dst, capturing per-edge ranks ----
        int q = blockIdx.x * 256 + threadIdx.x;
        if (q < n_quads) {
            int4 d = __ldg(dst4 + q);
            int4 r;
            r.x = atomicAdd(&g_counts[d.x], 1);
            r.y = atomicAdd(&g_counts[d.y], 1);
            r.z = atomicAdd(&g_counts[d.z], 1);
            r.w = atomicAdd(&g_counts[d.w], 1);
            ((int4*)g_rank)[q] = r;              // coalesced rank store
        }
        int t = n_quads * 4 + q;
        if (q < (n_edges - n_quads * 4))
            g_rank[t] = atomicAdd(&g_counts[dst[t]], 1);
    } else {
        // ---- W' = fp16(weight * cj): thread -> 8 floats -> one uint4 ----
        int i = ((int)blockIdx.x - hist_blocks) * 256 + threadIdx.x;  // uint4 idx
        int total = n_nodes * (FEAT4 / 2);       // 16 uint4 per row
        if (i < total) {
            int row = i >> 4;                    // 16 uint4 per row
            float s = __ldg(cj + row);           // warp-uniform broadcast
            float4 a = __ldg(weight4 + i * 2);
            float4 b = __ldg(weight4 + i * 2 + 1);
            __half2 h0 = __floats2half2_rn(a.x * s, a.y * s);
            __half2 h1 = __floats2half2_rn(a.z * s, a.w * s);
            __half2 h2 = __floats2half2_rn(b.x * s, b.y * s);
            __half2 h3 = __floats2half2_rn(b.z * s, b.w * s);
            uint4 p;
            p.x = *reinterpret_cast<unsigned int*>(&h0);
            p.y = *reinterpret_cast<unsigned int*>(&h1);
            p.z = *reinterpret_cast<unsigned int*>(&h2);
            p.w = *reinterpret_cast<unsigned int*>(&h3);
            reinterpret_cast<uint4*>(g_wh)[i] = p;
        }
    }
}

// ---------------- exclusive scan (single launch, publish/poll) ----------------
// Replay-proven structure (R5/R9/R10/R11 benches). 98 co-resident blocks.
// Block totals < 2^31; bit31 is the publish flag.

__global__ void __launch_bounds__(SCAN_BLOCK)
k_scan(int n) {
    __shared__ int warp_sums[32];
    __shared__ int s_prefix;
    int tid  = threadIdx.x;
    int i    = blockIdx.x * SCAN_BLOCK + tid;
    int lane = tid & 31, wid = tid >> 5;

    int v = (i < n) ? g_counts[i] : 0;

    int x = v;  // inclusive warp scan
    #pragma unroll
    for (int o = 1; o < 32; o <<= 1) {
        int y = __shfl_up_sync(0xFFFFFFFFu, x, o);
        if (lane >= o) x += y;
    }
    if (lane == 31) warp_sums[wid] = x;
    __syncthreads();

    if (wid == 0) {
        int w = warp_sums[lane];
        #pragma unroll
        for (int o = 1; o < 32; o <<= 1) {
            int y = __shfl_up_sync(0xFFFFFFFFu, w, o);
            if (lane >= o) w += y;
        }
        warp_sums[lane] = w;
        if (lane == 31)
            atomicExch(&g_pub[blockIdx.x], 0x80000000u | (unsigned)w);
    }
    __syncthreads();

    if (wid == 0) {
        int acc = 0;
        for (int b = lane; b < (int)blockIdx.x; b += 32) {
            unsigned int p;
            do { p = *(volatile unsigned int*)&g_pub[b]; }
            while (!(p & 0x80000000u));
            acc += (int)(p & 0x7FFFFFFFu);
        }
        #pragma unroll
        for (int o = 16; o > 0; o >>= 1)
            acc += __shfl_down_sync(0xFFFFFFFFu, acc, o);
        if (lane == 0) s_prefix = acc;
    }
    __syncthreads();

    int warp_off = (wid > 0) ? warp_sums[wid - 1] : 0;
    if (i < n) {
        int excl = s_prefix + warp_off + x - v;
        g_offsets[i] = excl;        // segment start
        g_cursor[i]  = excl + v;    // segment end
    }
}

// ---------------- scatter (atomic-free) ----------------

__global__ void __launch_bounds__(256)
k_scatter(const int4* __restrict__ src4,
          const int4* __restrict__ dst4, int n_quads,
          const int* __restrict__ src,
          const int* __restrict__ dst, int n_edges)
{
    int q = blockIdx.x * 256 + threadIdx.x;
    if (q < n_quads) {
        int4 s = __ldg(src4 + q);
        int4 d = __ldg(dst4 + q);
        int4 r = ((const int4*)g_rank)[q];
        g_edge_src[g_offsets[d.x] + r.x] = s.x;
        g_edge_src[g_offsets[d.y] + r.y] = s.y;
        g_edge_src[g_offsets[d.z] + r.z] = s.z;
        g_edge_src[g_offsets[d.w] + r.w] = s.w;
    }
    int t = n_quads * 4 + q;
    if (q < (n_edges - n_quads * 4))
        g_edge_src[g_offsets[dst[t]] + g_rank[t]] = src[t];

    // reset scan publish flags for the next graph replay
    if (blockIdx.x == 0 && threadIdx.x < MAX_SCAN_BLOCKS)
        g_pub[threadIdx.x] = 0u;
}

// ---------------- main gather-accumulate ----------------
// One warp per dst node; lane c owns halves [4c,4c+4) (one uint2 = 8B).
// Edge ids fetched 4-at-a-time via aligned int4 broadcast. Edge pairs are
// pre-reduced with HADD2 (one extra fp16 rounding; ~sqrt(2) error growth,
// measured base rel_err 2.07e-4 -> expected ~3.5e-4, gate is 1e-3).
// 32-bit indexing throughout (3.2M uint2 elements < 2^31 bytes).

__device__ __forceinline__ void acc_pair(float4& acc, uint2 pa, uint2 pb) {
    __half2 lo = __hadd2(*reinterpret_cast<__half2*>(&pa.x),
                         *reinterpret_cast<__half2*>(&pb.x));
    __half2 hi = __hadd2(*reinterpret_cast<__half2*>(&pa.y),
                         *reinterpret_cast<__half2*>(&pb.y));
    float2 f0 = __half22float2(lo);
    float2 f1 = __half22float2(hi);
    acc.x += f0.x; acc.y += f0.y; acc.z += f1.x; acc.w += f1.y;
}

__device__ __forceinline__ void acc_single(float4& acc, uint2 p) {
    float2 f0 = __half22float2(*reinterpret_cast<__half2*>(&p.x));
    float2 f1 = __half22float2(*reinterpret_cast<__half2*>(&p.y));
    acc.x += f0.x; acc.y += f0.y; acc.z += f1.x; acc.w += f1.y;
}

__global__ void __launch_bounds__(256)
k_gather(const float* __restrict__ ci,
         float4*      __restrict__ out4,
         int n_nodes)
{
    int gid  = blockIdx.x * blockDim.x + threadIdx.x;
    int node = gid >> 5;
    int c    = gid & 31;
    if (node >= n_nodes) return;

    int base = g_offsets[node];
    int end  = g_cursor[node];

    float4 acc = make_float4(0.f, 0.f, 0.f, 0.f);

    int j = base;
    // head: advance to 4-alignment for int4 id loads (<=3 iterations)
    while (j < end && (j & 3)) {
        uint2 p = __ldg(&g_wh[g_edge_src[j] * FEATH2 + c]);
        acc_single(acc, p);
        j++;
    }
    // main: 4 edges per iteration, one broadcast int4 id load
    for (; j + 3 < end; j += 4) {
        int4 s4 = __ldg(reinterpret_cast<const int4*>(g_edge_src + j));
        uint2 p0 = __ldg(&g_wh[s4.x * FEATH2 + c]);
        uint2 p1 = __ldg(&g_wh[s4.y * FEATH2 + c]);
        uint2 p2 = __ldg(&g_wh[s4.z * FEATH2 + c]);
        uint2 p3 = __ldg(&g_wh[s4.w * FEATH2 + c]);
        acc_pair(acc, p0, p1);
        acc_pair(acc, p2, p3);
    }
    // tail
    for (; j < end; j++) {
        uint2 p = __ldg(&g_wh[g_edge_src[j] * FEATH2 + c]);
        acc_single(acc, p);
    }

    float m = __ldg(ci + node);
    acc.x *= m; acc.y *= m; acc.z *= m; acc.w *= m;
    out4[node * FEAT4 + c] = acc;

    // restore zero-counts invariant for the next graph replay
    if (c == 0) g_counts[node] = 0;
}

// ---------------- launch ----------------

extern "C" void kernel_launch(void* const* d_in, const int* in_sizes, int n_in,
                              void* d_out, int out_size)
{
    const float4* weight4 = (const float4*)d_in[0];
    const float*  cj      = (const float*)d_in[1];
    const float*  ci      = (const float*)d_in[2];
    const int*    src     = (const int*)d_in[3];
    const int*    dst     = (const int*)d_in[4];
    float4*       out4    = (float4*)d_out;

    int n_nodes = in_sizes[1];   // cj is [N,1]
    int n_edges = in_sizes[3];
    int n_quads = n_edges / 4;

    const int B = 256;
    int hist_blocks = (n_quads + B - 1) / B;
    int conv_blocks = (n_nodes * (FEAT4 / 2) + B - 1) / B;   // uint4 granularity
    int scan_blocks = (n_nodes + SCAN_BLOCK - 1) / SCAN_BLOCK;

    k_pre<<<hist_blocks + conv_blocks, B>>>(weight4, cj, (const int4*)dst, dst,
                                            n_quads, n_edges, n_nodes, hist_blocks);
    k_scan<<<scan_blocks, SCAN_BLOCK>>>(n_nodes);
    k_scatter<<<hist_blocks, B>>>((const int4*)src, (const int4*)dst, n_quads,
                                  src, dst, n_edges);

    int64_t total_threads = (int64_t)n_nodes * 32;
    int gather_blocks = (int)((total_threads + B - 1) / B);
    k_gather<<<gather_blocks, B>>>(ci, out4, n_nodes);
}

// round 14
// speedup vs baseline: 1.0906x; 1.0309x over previous
#include <cuda_runtime.h>
#include <cuda_fp16.h>
#include <cstdint>

// Inputs (metadata order):
//   d_in[0] weight : float32 [N_NODES * 128]
//   d_in[1] cj     : float32 [N_NODES]
//   d_in[2] ci     : float32 [N_NODES]
//   d_in[3] src    : int32   [N_EDGES]
//   d_in[4] dst    : int32   [N_EDGES]
// Output: float32 [N_NODES * 128]
//
// h[d] = ci[d] * sum_{e: dst_e = d} weight[src_e] * cj[src_e]
//
// 4-kernel pipeline:
//   k_hist        : dst histogram with per-edge rank capture (atomic-bound,
//                   now UNfused from the BW-bound conversion)
//   k_scan        : exclusive scan; publish/poll cross-block prefix
//   k_scatter_conv: FUSED (a) pos = offsets[dst]+rank scatter (no atomics)
//                         (b) W' = fp16(weight*cj), 16B stores
//   k_gather      : one warp per dst node; 8-deep unrolled fp16 gathers
//                   (2x int4 id broadcast), HADD2 pair pre-reduction,
//                   fp32 accumulation, single 512B store

static constexpr int MAX_NODES  = 100000;
static constexpr int MAX_EDGES  = 1600000;
static constexpr int FEAT4      = 32;           // 128 floats = 32 float4
static constexpr int FEATH2     = 32;           // 128 halves = 32 uint2
static constexpr int SCAN_BLOCK = 1024;
static constexpr int MAX_SCAN_BLOCKS = (MAX_NODES + SCAN_BLOCK - 1) / SCAN_BLOCK; // 98

__device__ int g_counts[MAX_NODES];             // zero-init; re-zeroed by gather
__device__ int g_offsets[MAX_NODES];            // segment start
__device__ int g_cursor[MAX_NODES];             // segment end
__device__ unsigned int g_pub[MAX_SCAN_BLOCKS]; // zero-init; re-zeroed by scatter
__device__ int g_rank[MAX_EDGES];               // per-edge rank within its dst
__device__ __align__(16) int g_edge_src[MAX_EDGES];  // dst-sorted src ids
__device__ uint2 g_wh[MAX_NODES * FEATH2];      // fp16 W' = weight*cj (25.6 MB)

// ---------------- histogram with rank capture ----------------

__global__ void __launch_bounds__(256)
k_hist(const int4* __restrict__ dst4, int n_quads,
       const int* __restrict__ dst, int n_edges)
{
    int q = blockIdx.x * 256 + threadIdx.x;
    if (q < n_quads) {
        int4 d = __ldg(dst4 + q);
        int4 r;
        r.x = atomicAdd(&g_counts[d.x], 1);
        r.y = atomicAdd(&g_counts[d.y], 1);
        r.z = atomicAdd(&g_counts[d.z], 1);
        r.w = atomicAdd(&g_counts[d.w], 1);
        ((int4*)g_rank)[q] = r;                  // coalesced rank store
    }
    int t = n_quads * 4 + q;
    if (q < (n_edges - n_quads * 4))
        g_rank[t] = atomicAdd(&g_counts[dst[t]], 1);
}

// ---------------- exclusive scan (single launch, publish/poll) ----------------
// Replay-proven structure (R5/R9-R12 benches). 98 co-resident blocks.
// Block totals < 2^31; bit31 is the publish flag.

__global__ void __launch_bounds__(SCAN_BLOCK)
k_scan(int n) {
    __shared__ int warp_sums[32];
    __shared__ int s_prefix;
    int tid  = threadIdx.x;
    int i    = blockIdx.x * SCAN_BLOCK + tid;
    int lane = tid & 31, wid = tid >> 5;

    int v = (i < n) ? g_counts[i] : 0;

    int x = v;  // inclusive warp scan
    #pragma unroll
    for (int o = 1; o < 32; o <<= 1) {
        int y = __shfl_up_sync(0xFFFFFFFFu, x, o);
        if (lane >= o) x += y;
    }
    if (lane == 31) warp_sums[wid] = x;
    __syncthreads();

    if (wid == 0) {
        int w = warp_sums[lane];
        #pragma unroll
        for (int o = 1; o < 32; o <<= 1) {
            int y = __shfl_up_sync(0xFFFFFFFFu, w, o);
            if (lane >= o) w += y;
        }
        warp_sums[lane] = w;
        if (lane == 31)
            atomicExch(&g_pub[blockIdx.x], 0x80000000u | (unsigned)w);
    }
    __syncthreads();

    if (wid == 0) {
        int acc = 0;
        for (int b = lane; b < (int)blockIdx.x; b += 32) {
            unsigned int p;
            do { p = *(volatile unsigned int*)&g_pub[b]; }
            while (!(p & 0x80000000u));
            acc += (int)(p & 0x7FFFFFFFu);
        }
        #pragma unroll
        for (int o = 16; o > 0; o >>= 1)
            acc += __shfl_down_sync(0xFFFFFFFFu, acc, o);
        if (lane == 0) s_prefix = acc;
    }
    __syncthreads();

    int warp_off = (wid > 0) ? warp_sums[wid - 1] : 0;
    if (i < n) {
        int excl = s_prefix + warp_off + x - v;
        g_offsets[i] = excl;        // segment start
        g_cursor[i]  = excl + v;    // segment end
    }
}

// ---------------- fused scatter + fp16 conversion ----------------
// Scatter blocks [0, scat_blocks) are latency-bound; conversion blocks are
// bandwidth-bound; pairing them fills complementary resources.

__global__ void __launch_bounds__(256)
k_scatter_conv(const int4* __restrict__ src4,
               const int4* __restrict__ dst4, int n_quads,
               const int* __restrict__ src,
               const int* __restrict__ dst, int n_edges,
               const float4* __restrict__ weight4,
               const float*  __restrict__ cj,
               int n_nodes, int scat_blocks)
{
    if ((int)blockIdx.x < scat_blocks) {
        int q = blockIdx.x * 256 + threadIdx.x;
        if (q < n_quads) {
            int4 s = __ldg(src4 + q);
            int4 d = __ldg(dst4 + q);
            int4 r = ((const int4*)g_rank)[q];
            g_edge_src[g_offsets[d.x] + r.x] = s.x;
            g_edge_src[g_offsets[d.y] + r.y] = s.y;
            g_edge_src[g_offsets[d.z] + r.z] = s.z;
            g_edge_src[g_offsets[d.w] + r.w] = s.w;
        }
        int t = n_quads * 4 + q;
        if (q < (n_edges - n_quads * 4))
            g_edge_src[g_offsets[dst[t]] + g_rank[t]] = src[t];

        // reset scan publish flags for the next graph replay
        if (blockIdx.x == 0 && threadIdx.x < MAX_SCAN_BLOCKS)
            g_pub[threadIdx.x] = 0u;
    } else {
        // W' = fp16(weight * cj): thread -> 8 floats -> one uint4 store
        int i = ((int)blockIdx.x - scat_blocks) * 256 + threadIdx.x;
        int total = n_nodes * (FEAT4 / 2);       // 16 uint4 per row
        if (i < total) {
            int row = i >> 4;
            float s = __ldg(cj + row);           // warp-uniform broadcast
            float4 a = __ldg(weight4 + i * 2);
            float4 b = __ldg(weight4 + i * 2 + 1);
            __half2 h0 = __floats2half2_rn(a.x * s, a.y * s);
            __half2 h1 = __floats2half2_rn(a.z * s, a.w * s);
            __half2 h2 = __floats2half2_rn(b.x * s, b.y * s);
            __half2 h3 = __floats2half2_rn(b.z * s, b.w * s);
            uint4 p;
            p.x = *reinterpret_cast<unsigned int*>(&h0);
            p.y = *reinterpret_cast<unsigned int*>(&h1);
            p.z = *reinterpret_cast<unsigned int*>(&h2);
            p.w = *reinterpret_cast<unsigned int*>(&h3);
            reinterpret_cast<uint4*>(g_wh)[i] = p;
        }
    }
}

// ---------------- main gather-accumulate ----------------
// One warp per dst node; lane c owns halves [4c,4c+4) (one uint2 = 8B).
// 8 edges per main iteration (two int4 id broadcasts, 8 outstanding gathers)
// to deepen MLP on the L2-latency critical path. HADD2 pair pre-reduction
// (measured rel_err 2.87e-4, gate 1e-3). 32-bit indexing.

__device__ __forceinline__ void acc_pair(float4& acc, uint2 pa, uint2 pb) {
    __half2 lo = __hadd2(*reinterpret_cast<__half2*>(&pa.x),
                         *reinterpret_cast<__half2*>(&pb.x));
    __half2 hi = __hadd2(*reinterpret_cast<__half2*>(&pa.y),
                         *reinterpret_cast<__half2*>(&pb.y));
    float2 f0 = __half22float2(lo);
    float2 f1 = __half22float2(hi);
    acc.x += f0.x; acc.y += f0.y; acc.z += f1.x; acc.w += f1.y;
}

__device__ __forceinline__ void acc_single(float4& acc, uint2 p) {
    float2 f0 = __half22float2(*reinterpret_cast<__half2*>(&p.x));
    float2 f1 = __half22float2(*reinterpret_cast<__half2*>(&p.y));
    acc.x += f0.x; acc.y += f0.y; acc.z += f1.x; acc.w += f1.y;
}

__global__ void __launch_bounds__(256)
k_gather(const float* __restrict__ ci,
         float4*      __restrict__ out4,
         int n_nodes)
{
    int gid  = blockIdx.x * blockDim.x + threadIdx.x;
    int node = gid >> 5;
    int c    = gid & 31;
    if (node >= n_nodes) return;

    int base = g_offsets[node];
    int end  = g_cursor[node];

    float4 acc = make_float4(0.f, 0.f, 0.f, 0.f);

    int j = base;
    // head: advance to 4-alignment for int4 id loads (<=3 iterations)
    while (j < end && (j & 3)) {
        uint2 p = __ldg(&g_wh[g_edge_src[j] * FEATH2 + c]);
        acc_single(acc, p);
        j++;
    }
    // main: 8 edges per iteration, 8 gathers in flight
    for (; j + 7 < end; j += 8) {
        int4 sa = __ldg(reinterpret_cast<const int4*>(g_edge_src + j));
        int4 sb = __ldg(reinterpret_cast<const int4*>(g_edge_src + j + 4));
        uint2 p0 = __ldg(&g_wh[sa.x * FEATH2 + c]);
        uint2 p1 = __ldg(&g_wh[sa.y * FEATH2 + c]);
        uint2 p2 = __ldg(&g_wh[sa.z * FEATH2 + c]);
        uint2 p3 = __ldg(&g_wh[sa.w * FEATH2 + c]);
        uint2 p4 = __ldg(&g_wh[sb.x * FEATH2 + c]);
        uint2 p5 = __ldg(&g_wh[sb.y * FEATH2 + c]);
        uint2 p6 = __ldg(&g_wh[sb.z * FEATH2 + c]);
        uint2 p7 = __ldg(&g_wh[sb.w * FEATH2 + c]);
        acc_pair(acc, p0, p1);
        acc_pair(acc, p2, p3);
        acc_pair(acc, p4, p5);
        acc_pair(acc, p6, p7);
    }
    // 4-edge step
    if (j + 3 < end) {
        int4 s4 = __ldg(reinterpret_cast<const int4*>(g_edge_src + j));
        uint2 p0 = __ldg(&g_wh[s4.x * FEATH2 + c]);
        uint2 p1 = __ldg(&g_wh[s4.y * FEATH2 + c]);
        uint2 p2 = __ldg(&g_wh[s4.z * FEATH2 + c]);
        uint2 p3 = __ldg(&g_wh[s4.w * FEATH2 + c]);
        acc_pair(acc, p0, p1);
        acc_pair(acc, p2, p3);
        j += 4;
    }
    // tail
    for (; j < end; j++) {
        uint2 p = __ldg(&g_wh[g_edge_src[j] * FEATH2 + c]);
        acc_single(acc, p);
    }

    float m = __ldg(ci + node);
    acc.x *= m; acc.y *= m; acc.z *= m; acc.w *= m;
    out4[node * FEAT4 + c] = acc;

    // restore zero-counts invariant for the next graph replay
    if (c == 0) g_counts[node] = 0;
}

// ---------------- launch ----------------

extern "C" void kernel_launch(void* const* d_in, const int* in_sizes, int n_in,
                              void* d_out, int out_size)
{
    const float4* weight4 = (const float4*)d_in[0];
    const float*  cj      = (const float*)d_in[1];
    const float*  ci      = (const float*)d_in[2];
    const int*    src     = (const int*)d_in[3];
    const int*    dst     = (const int*)d_in[4];
    float4*       out4    = (float4*)d_out;

    int n_nodes = in_sizes[1];   // cj is [N,1]
    int n_edges = in_sizes[3];
    int n_quads = n_edges / 4;

    const int B = 256;
    int scat_blocks = (n_quads + B - 1) / B;
    int conv_blocks = (n_nodes * (FEAT4 / 2) + B - 1) / B;   // uint4 granularity
    int scan_blocks = (n_nodes + SCAN_BLOCK - 1) / SCAN_BLOCK;

    k_hist<<<scat_blocks, B>>>((const int4*)dst, n_quads, dst, n_edges);
    k_scan<<<scan_blocks, SCAN_BLOCK>>>(n_nodes);
    k_scatter_conv<<<scat_blocks + conv_blocks, B>>>(
        (const int4*)src, (const int4*)dst, n_quads, src, dst, n_edges,
        weight4, cj, n_nodes, scat_blocks);

    int64_t total_threads = (int64_t)n_nodes * 32;
    int gather_blocks = (int)((total_threads + B - 1) / B);
    k_gather<<<gather_blocks, B>>>(ci, out4, n_nodes);
}